// round 10
// baseline (speedup 1.0000x reference)
#include <cuda_runtime.h>
#include <cuda_fp16.h>
#include <cstdint>
#include <cstddef>

#define S_LEN 128
#define BATCH 32
#define HID   200
#define EMB   200
#define VOCAB 50257
#define KP    208              // K padded to multiple of 16 for mma
#define M_TOT (S_LEN*BATCH)    // 4096

typedef unsigned long long ull;

// ---------------- scratch (device globals; no allocation) ----------------
__device__ float  g_Z0[M_TOT*HID];
__device__ float  g_Z1[M_TOT*HID];
__device__ float  g_Y0[M_TOT*HID];
__device__ float  g_Y1[M_TOT*HID];
__device__ __half g_A16[M_TOT*KP];          // pad cols [200,208) stay zero (static init, never written)
__device__ __half g_B16[(size_t)VOCAB*KP];

// ---------------- packed f32x2 helpers (Blackwell) ----------------
__device__ __forceinline__ ull fma2(ull a, ull b, ull c) {
    ull d;
    asm("fma.rn.f32x2 %0, %1, %2, %3;" : "=l"(d) : "l"(a), "l"(b), "l"(c));
    return d;
}
__device__ __forceinline__ float f2sum(ull v) {
    float lo, hi;
    asm("mov.b64 {%0,%1}, %2;" : "=f"(lo), "=f"(hi) : "l"(v));
    return lo + hi;
}
__device__ __forceinline__ float fast_tanh(float x) {
    float e = __expf(2.f*x);
    return 1.f - __fdividef(2.f, e + 1.f);
}

// ---------------- K1: embedding gather + Z0 = emb @ W_ih0^T ----------------
// 256 threads: warp w -> (bh = w&1, jg = w>>1); lane -> (bl = lane&15, kh = lane>>4).
// Thread holds its 100-float x-half in registers; W rows streamed as broadcast loads;
// k-half reduction via shfl_xor(16).
__global__ __launch_bounds__(256) void z0_kernel(const int* __restrict__ X,
                                                 const float* __restrict__ embW,
                                                 const float* __restrict__ Wih) {
    __shared__ __align__(16) float xs[BATCH][KP];
    int s = blockIdx.x, tid = threadIdx.x;
    for (int i = tid; i < BATCH*EMB; i += 256) {
        int b = i / EMB, d = i - b*EMB;
        xs[b][d] = embW[(size_t)X[s*BATCH + b]*EMB + d];
    }
    __syncthreads();

    int lane = tid & 31, warp = tid >> 5;
    int bl = lane & 15, kh = lane >> 4;
    int bh = warp & 1, jg = warp >> 1;     // jg in 0..3, 50 j's each
    int b  = bh*16 + bl;

    ulonglong2 xr[25];                     // 100 floats
    const ulonglong2* xp = (const ulonglong2*)(&xs[b][0] + kh*100);
    #pragma unroll
    for (int i = 0; i < 25; i++) xr[i] = xp[i];

    float* zrow = g_Z0 + (size_t)s*BATCH*HID;
    for (int jj = 0; jj < 50; jj++) {
        int j = jg*50 + jj;
        const ulonglong2* wp = (const ulonglong2*)(Wih + (size_t)j*EMB + kh*100);
        ull a0 = 0, a1 = 0, a2 = 0, a3 = 0;
        #pragma unroll
        for (int i = 0; i < 25; i++) {
            ulonglong2 w = wp[i];
            if (i & 1) { a2 = fma2(w.x, xr[i].x, a2); a3 = fma2(w.y, xr[i].y, a3); }
            else       { a0 = fma2(w.x, xr[i].x, a0); a1 = fma2(w.y, xr[i].y, a1); }
        }
        float acc = (f2sum(a0) + f2sum(a2)) + (f2sum(a1) + f2sum(a3));
        acc += __shfl_xor_sync(0xffffffffu, acc, 16);
        if (kh == 0) zrow[b*HID + j] = acc;
    }
}

// ---------------- K3: Z1 = y0 @ W_ih1^T (same structure) ----------------
__global__ __launch_bounds__(256) void z1_kernel(const float* __restrict__ Wih) {
    __shared__ __align__(16) float xs[BATCH][KP];
    int s = blockIdx.x, tid = threadIdx.x;
    for (int i = tid; i < BATCH*HID; i += 256) {
        int b = i / HID, d = i - b*HID;
        xs[b][d] = g_Y0[((size_t)s*BATCH + b)*HID + d];
    }
    __syncthreads();

    int lane = tid & 31, warp = tid >> 5;
    int bl = lane & 15, kh = lane >> 4;
    int bh = warp & 1, jg = warp >> 1;
    int b  = bh*16 + bl;

    ulonglong2 xr[25];
    const ulonglong2* xp = (const ulonglong2*)(&xs[b][0] + kh*100);
    #pragma unroll
    for (int i = 0; i < 25; i++) xr[i] = xp[i];

    float* zrow = g_Z1 + (size_t)s*BATCH*HID;
    for (int jj = 0; jj < 50; jj++) {
        int j = jg*50 + jj;
        const ulonglong2* wp = (const ulonglong2*)(Wih + (size_t)j*HID + kh*100);
        ull a0 = 0, a1 = 0, a2 = 0, a3 = 0;
        #pragma unroll
        for (int i = 0; i < 25; i++) {
            ulonglong2 w = wp[i];
            if (i & 1) { a2 = fma2(w.x, xr[i].x, a2); a3 = fma2(w.y, xr[i].y, a3); }
            else       { a0 = fma2(w.x, xr[i].x, a0); a1 = fma2(w.y, xr[i].y, a1); }
        }
        float acc = (f2sum(a0) + f2sum(a2)) + (f2sum(a1) + f2sum(a3));
        acc += __shfl_xor_sync(0xffffffffu, acc, 16);
        if (kh == 0) zrow[b*HID + j] = acc;
    }
}

// ---------------- K2/K4: batch-parallel recurrence. One CTA per batch row. ----------------
// Thread t0: j = t0>>1, kh = t0&1. W_hh row-half in 100 regs (f32x2 packed);
// h double-buffered in smem; ONE __syncthreads per step. Globals selected device-side.
#define RNN_THREADS 416
__global__ __launch_bounds__(RNN_THREADS, 1)
void rnn_fast_kernel(const float* __restrict__ Whh, const float* __restrict__ h_init,
                     int layer) {
    __shared__ __align__(16) float hs[2][HID];
    const float* __restrict__ Z = layer ? g_Z1 : g_Z0;
    float* __restrict__ Y       = layer ? g_Y1 : g_Y0;

    const int b   = blockIdx.x;
    const int t0  = threadIdx.x;
    const int j   = t0 >> 1;
    const int kh  = t0 & 1;
    const bool valid = (j < HID);

    // Pin this thread's W_hh row-half (packed) in registers.
    const ulonglong2* wp = (const ulonglong2*)(Whh + (size_t)(valid ? j : 0)*HID + kh*100);
    ulonglong2 wreg[25];
    #pragma unroll
    for (int i = 0; i < 25; i++) wreg[i] = wp[i];

    for (int i = t0; i < HID; i += RNN_THREADS) hs[0][i] = h_init[b*HID + i];
    __syncthreads();

    float zc = (valid && kh == 0) ? Z[(size_t)b*HID + j] : 0.f;

    for (int t = 0; t < S_LEN; t++) {
        const int cur = t & 1, nxt = cur ^ 1;
        float zn = 0.f;
        if (t + 1 < S_LEN && valid && kh == 0)
            zn = Z[((size_t)(t+1)*BATCH + b)*HID + j];

        const ulonglong2* h2 = (const ulonglong2*)(hs[cur] + kh*100);
        ull a0 = 0, a1 = 0;
        #pragma unroll
        for (int i = 0; i < 25; i++) {
            ulonglong2 h = h2[i];
            a0 = fma2(wreg[i].x, h.x, a0);
            a1 = fma2(wreg[i].y, h.y, a1);
        }
        float acc = f2sum(a0) + f2sum(a1);
        float other = __shfl_down_sync(0xffffffffu, acc, 1);  // kh=1 partial -> kh=0 lane
        if (valid && kh == 0) {
            float v = fast_tanh(zc + acc + other);
            hs[nxt][j] = v;
            Y[((size_t)t*BATCH + b)*HID + j] = v;
            if (layer)
                g_A16[((size_t)t*BATCH + b)*KP + j] = __float2half_rn(v);
        }
        zc = zn;
        __syncthreads();
    }
}

// ---------------- convB: decoder weights -> fp16, K padded to 208 ----------------
__global__ void convB_kernel(const float* __restrict__ W) {
    size_t idx = (size_t)blockIdx.x*256 + threadIdx.x;
    if (idx >= (size_t)VOCAB*KP) return;
    size_t r = idx / KP; int c = (int)(idx % KP);
    g_B16[idx] = (c < HID) ? __float2half_rn(W[r*HID + c]) : __float2half_rn(0.f);
}

// ---------------- hidden_out = stack(y0[S-1], y1[S-1]) ----------------
__global__ void hidden_kernel(float* __restrict__ out) {
    int idx = blockIdx.x*256 + threadIdx.x;
    if (idx >= 2*BATCH*HID) return;
    int l = idx / (BATCH*HID), r = idx % (BATCH*HID);
    const float* Y = l ? g_Y1 : g_Y0;
    out[(size_t)M_TOT*VOCAB + idx] = Y[(S_LEN-1)*BATCH*HID + r];
}

// ---------------- K5: decode GEMM, fp16 mma.sync + ldmatrix, fp32 accumulate ----------------
// C[4096, 50257] = A16[4096, 208] * B16[50257, 208]^T + bias
#define SST 216   // smem row stride in halves (conflict-mitigating pad)
__device__ __forceinline__ void ldsm_x4(uint32_t& r0, uint32_t& r1, uint32_t& r2, uint32_t& r3,
                                        uint32_t addr) {
    asm volatile("ldmatrix.sync.aligned.m8n8.x4.shared.b16 {%0,%1,%2,%3}, [%4];"
                 : "=r"(r0), "=r"(r1), "=r"(r2), "=r"(r3) : "r"(addr));
}

__global__ __launch_bounds__(256, 2) void decode_kernel(const float* __restrict__ bias,
                                                        float* __restrict__ out) {
    extern __shared__ __half smemh[];
    __half* As = smemh;             // [128][SST]
    __half* Bs = smemh + 128*SST;   // [128][SST]
    int tid = threadIdx.x;
    int bn = blockIdx.x, bm = blockIdx.y;

    for (int i = tid; i < 128*26; i += 256) {
        int r = i/26, c = i%26;
        uint4 v = *(const uint4*)(g_A16 + (size_t)(bm*128 + r)*KP + c*8);
        *(uint4*)(As + r*SST + c*8) = v;
    }
    for (int i = tid; i < 128*26; i += 256) {
        int r = i/26, c = i%26;
        int gn = bn*128 + r;
        uint4 v = make_uint4(0u,0u,0u,0u);
        if (gn < VOCAB) v = *(const uint4*)(g_B16 + (size_t)gn*KP + c*8);
        *(uint4*)(Bs + r*SST + c*8) = v;
    }
    __syncthreads();

    int warp = tid >> 5, lane = tid & 31;
    int wm = warp >> 2, wn = warp & 3;     // 2 x 4 warp grid, warp tile 64x32
    int lr = lane >> 2, lc = lane & 3;

    float acc[4][4][4];
    #pragma unroll
    for (int a=0;a<4;a++)
        #pragma unroll
        for (int b=0;b<4;b++)
            #pragma unroll
            for (int c=0;c<4;c++) acc[a][b][c]=0.f;

    // ldmatrix lane-address bases.
    // A (m16k16 per mf): lanes 0-7 rows 0-7@k0, 8-15 rows 8-15@k0, 16-23 rows 0-7@k+8, 24-31 rows 8-15@k+8
    //   -> results r0..r3 = a0..a3 of the mma A fragment.
    // B (two n8k16 frags per x4): lanes 0-7: nf-even rows@k0; 8-15: nf-even rows@k+8;
    //   16-23: nf-odd rows@k0; 24-31: nf-odd rows@k+8 -> r0..r3 = bf[e][0], bf[e][1], bf[o][0], bf[o][1].
    uint32_t smemA = (uint32_t)__cvta_generic_to_shared(As);
    uint32_t smemB = (uint32_t)__cvta_generic_to_shared(Bs);
    uint32_t aBase = smemA + (uint32_t)(((wm*64 + (lane & 15))*SST + (lane >> 4)*8) * 2);
    uint32_t bBase = smemB + (uint32_t)(((wn*32 + (lane >> 4)*8 + (lane & 7))*SST
                                         + ((lane >> 3) & 1)*8) * 2);

    #pragma unroll
    for (int ks = 0; ks < 13; ks++) {
        uint32_t koff = (uint32_t)(ks*16*2);     // bytes
        uint32_t a[4][4], bf[4][2];
        #pragma unroll
        for (int mf = 0; mf < 4; mf++)
            ldsm_x4(a[mf][0], a[mf][1], a[mf][2], a[mf][3],
                    aBase + (uint32_t)(mf*16*SST*2) + koff);
        ldsm_x4(bf[0][0], bf[0][1], bf[1][0], bf[1][1], bBase + koff);
        ldsm_x4(bf[2][0], bf[2][1], bf[3][0], bf[3][1],
                bBase + (uint32_t)(16*SST*2) + koff);

        #pragma unroll
        for (int mf = 0; mf < 4; mf++)
            #pragma unroll
            for (int nf = 0; nf < 4; nf++)
                asm volatile(
                    "mma.sync.aligned.m16n8k16.row.col.f32.f16.f16.f32 "
                    "{%0,%1,%2,%3}, {%4,%5,%6,%7}, {%8,%9}, {%0,%1,%2,%3};"
                    : "+f"(acc[mf][nf][0]), "+f"(acc[mf][nf][1]),
                      "+f"(acc[mf][nf][2]), "+f"(acc[mf][nf][3])
                    : "r"(a[mf][0]), "r"(a[mf][1]), "r"(a[mf][2]), "r"(a[mf][3]),
                      "r"(bf[nf][0]), "r"(bf[nf][1]));
    }

    #pragma unroll
    for (int mf = 0; mf < 4; mf++) {
        int gm = bm*128 + wm*64 + mf*16 + lr;
        #pragma unroll
        for (int nf = 0; nf < 4; nf++) {
            int gn = bn*128 + wn*32 + nf*8 + lc*2;
            if (gn < VOCAB) {
                float b0 = bias[gn];
                out[(size_t)gm*VOCAB + gn]     = acc[mf][nf][0] + b0;
                out[(size_t)(gm+8)*VOCAB + gn] = acc[mf][nf][2] + b0;
            }
            if (gn+1 < VOCAB) {
                float b1 = bias[gn+1];
                out[(size_t)gm*VOCAB + gn+1]     = acc[mf][nf][1] + b1;
                out[(size_t)(gm+8)*VOCAB + gn+1] = acc[mf][nf][3] + b1;
            }
        }
    }
}

// ---------------- launch ----------------
extern "C" void kernel_launch(void* const* d_in, const int* in_sizes, int n_in,
                              void* d_out, int out_size) {
    (void)in_sizes; (void)n_in; (void)out_size;
    const int*   X      = (const int*)d_in[0];
    const float* hidden = (const float*)d_in[1];
    const float* embW   = (const float*)d_in[2];
    const float* Wih0   = (const float*)d_in[3];
    const float* Whh0   = (const float*)d_in[4];
    const float* Wih1   = (const float*)d_in[5];
    const float* Whh1   = (const float*)d_in[6];
    const float* decW   = (const float*)d_in[7];
    const float* decb   = (const float*)d_in[8];
    float* out = (float*)d_out;

    convB_kernel<<<(int)(((size_t)VOCAB*KP + 255)/256), 256>>>(decW);
    z0_kernel<<<S_LEN, 256>>>(X, embW, Wih0);

    rnn_fast_kernel<<<BATCH, RNN_THREADS>>>(Whh0, hidden, 0);
    z1_kernel<<<S_LEN, 256>>>(Wih1);
    rnn_fast_kernel<<<BATCH, RNN_THREADS>>>(Whh1, hidden + BATCH*HID, 1);

    hidden_kernel<<<(2*BATCH*HID + 255)/256, 256>>>(out);

    cudaFuncSetAttribute(decode_kernel, cudaFuncAttributeMaxDynamicSharedMemorySize,
                         2*128*SST*(int)sizeof(__half));
    dim3 grid((VOCAB + 127)/128, M_TOT/128);   // 393 x 32
    decode_kernel<<<grid, 256, 2*128*SST*(int)sizeof(__half)>>>(decb, out);
}

// round 11
// speedup vs baseline: 1.4313x; 1.4313x over previous
#include <cuda_runtime.h>
#include <cuda_fp16.h>
#include <cstdint>
#include <cstddef>

#define S_LEN 128
#define BATCH 32
#define HID   200
#define EMB   200
#define VOCAB 50257
#define KP    208              // K padded to multiple of 16 for mma
#define M_TOT (S_LEN*BATCH)    // 4096

// ---------------- scratch (device globals; no allocation) ----------------
__device__ float  g_Z0[M_TOT*HID];
__device__ float  g_Z1[M_TOT*HID];
__device__ float  g_Y0[M_TOT*HID];
__device__ float  g_Y1[M_TOT*HID];
__device__ __half g_A16[M_TOT*KP];          // pad cols [200,208) stay zero (static init, never written)
__device__ __half g_B16[(size_t)VOCAB*KP];

// ============== K1: embedding gather + Z0 = emb @ W_ih0^T ==============
// x transposed in smem: xs[k][b], row stride 33 -> lane b at depth k hits bank
// (k+b)%32: conflict-free scalar LDS. W rows are warp-uniform float4 LDG.
// Warp w owns j-range [w*25, w*25+25); lane = b. 4 independent FFMA chains.
__global__ __launch_bounds__(256) void z0_kernel(const int* __restrict__ X,
                                                 const float* __restrict__ embW,
                                                 const float* __restrict__ Wih) {
    __shared__ float xs[EMB][33];
    int s = blockIdx.x, tid = threadIdx.x;
    for (int i = tid; i < BATCH*EMB; i += 256) {
        int b = i / EMB, d = i - b*EMB;              // consecutive d -> conflict-free writes
        xs[d][b] = embW[(size_t)X[s*BATCH + b]*EMB + d];
    }
    __syncthreads();

    int b = tid & 31, jg = tid >> 5;                 // 8 warps x 25 j
    float* zrow = g_Z0 + (size_t)s*BATCH*HID;
    for (int jj = 0; jj < 25; jj++) {
        int j = jg*25 + jj;
        const float4* wr = (const float4*)(Wih + (size_t)j*EMB);
        float a0 = 0.f, a1 = 0.f, a2 = 0.f, a3 = 0.f;
        #pragma unroll 10
        for (int k4 = 0; k4 < EMB/4; k4++) {
            float4 w = wr[k4];                       // warp-uniform
            a0 += w.x * xs[4*k4+0][b];
            a1 += w.y * xs[4*k4+1][b];
            a2 += w.z * xs[4*k4+2][b];
            a3 += w.w * xs[4*k4+3][b];
        }
        zrow[b*HID + j] = (a0 + a1) + (a2 + a3);
    }
}

// ============== K3: Z1 = y0 @ W_ih1^T (same structure) ==============
__global__ __launch_bounds__(256) void z1_kernel(const float* __restrict__ Wih) {
    __shared__ float xs[HID][33];
    int s = blockIdx.x, tid = threadIdx.x;
    for (int i = tid; i < BATCH*HID; i += 256) {
        int b = i / HID, d = i - b*HID;
        xs[d][b] = g_Y0[((size_t)s*BATCH + b)*HID + d];
    }
    __syncthreads();

    int b = tid & 31, jg = tid >> 5;
    float* zrow = g_Z1 + (size_t)s*BATCH*HID;
    for (int jj = 0; jj < 25; jj++) {
        int j = jg*25 + jj;
        const float4* wr = (const float4*)(Wih + (size_t)j*HID);
        float a0 = 0.f, a1 = 0.f, a2 = 0.f, a3 = 0.f;
        #pragma unroll 10
        for (int k4 = 0; k4 < HID/4; k4++) {
            float4 w = wr[k4];
            a0 += w.x * xs[4*k4+0][b];
            a1 += w.y * xs[4*k4+1][b];
            a2 += w.z * xs[4*k4+2][b];
            a3 += w.w * xs[4*k4+3][b];
        }
        zrow[b*HID + j] = (a0 + a1) + (a2 + a3);
    }
}

// ====== K2/K4: batch-parallel recurrence (R9-proven version, unchanged) ======
// One CTA per batch row. Thread t0: j = t0>>1, kh = t0&1. W_hh row-half pinned in
// 100 regs; h double-buffered in smem; ONE __syncthreads per step.
#define RNN_THREADS 416
__global__ __launch_bounds__(RNN_THREADS, 1)
void rnn_fast_kernel(const float* __restrict__ Whh, const float* __restrict__ h_init,
                     int layer) {
    __shared__ __align__(16) float hs[2][HID];
    const float* __restrict__ Z = layer ? g_Z1 : g_Z0;
    float* __restrict__ Y       = layer ? g_Y1 : g_Y0;

    const int b   = blockIdx.x;
    const int t0  = threadIdx.x;
    const int j   = t0 >> 1;
    const int kh  = t0 & 1;
    const bool valid = (j < HID);

    const float* wp = Whh + (size_t)(valid ? j : 0)*HID + kh*100;
    float w[100];
    #pragma unroll
    for (int i = 0; i < 100; i++) w[i] = wp[i];

    for (int i = t0; i < HID; i += RNN_THREADS) hs[0][i] = h_init[b*HID + i];
    __syncthreads();

    float zc = (valid && kh == 0) ? Z[(size_t)b*HID + j] : 0.f;

    for (int t = 0; t < S_LEN; t++) {
        const int cur = t & 1, nxt = cur ^ 1;
        float zn = 0.f;
        if (t + 1 < S_LEN && valid && kh == 0)
            zn = Z[((size_t)(t+1)*BATCH + b)*HID + j];

        float a0 = 0.f, a1 = 0.f, a2 = 0.f, a3 = 0.f;
        const float4* h4 = (const float4*)(hs[cur] + kh*100);
        #pragma unroll
        for (int i = 0; i < 25; i++) {
            float4 h = h4[i];
            a0 += w[4*i+0]*h.x;
            a1 += w[4*i+1]*h.y;
            a2 += w[4*i+2]*h.z;
            a3 += w[4*i+3]*h.w;
        }
        float acc = (a0 + a1) + (a2 + a3);
        float other = __shfl_down_sync(0xffffffffu, acc, 1);  // kh=1 -> kh=0 lane
        if (valid && kh == 0) {
            float v = tanhf(zc + acc + other);
            hs[nxt][j] = v;
            Y[((size_t)t*BATCH + b)*HID + j] = v;
            if (layer)
                g_A16[((size_t)t*BATCH + b)*KP + j] = __float2half_rn(v);
        }
        zc = zn;
        __syncthreads();
    }
}

// ---------------- convB: decoder weights -> fp16, K padded to 208 ----------------
__global__ void convB_kernel(const float* __restrict__ W) {
    size_t idx = (size_t)blockIdx.x*256 + threadIdx.x;
    if (idx >= (size_t)VOCAB*KP) return;
    size_t r = idx / KP; int c = (int)(idx % KP);
    g_B16[idx] = (c < HID) ? __float2half_rn(W[r*HID + c]) : __float2half_rn(0.f);
}

// ---------------- hidden_out = stack(y0[S-1], y1[S-1]) ----------------
__global__ void hidden_kernel(float* __restrict__ out) {
    int idx = blockIdx.x*256 + threadIdx.x;
    if (idx >= 2*BATCH*HID) return;
    int l = idx / (BATCH*HID), r = idx % (BATCH*HID);
    const float* Y = l ? g_Y1 : g_Y0;
    out[(size_t)M_TOT*VOCAB + idx] = Y[(S_LEN-1)*BATCH*HID + r];
}

// ====== K5: decode GEMM (R9-proven scalar-LDS version, unchanged) ======
// C[4096, 50257] = A16[4096, 208] * B16[50257, 208]^T + bias
#define SST 216   // smem row stride in halves (conflict-mitigating pad)
__global__ __launch_bounds__(256, 2) void decode_kernel(const float* __restrict__ bias,
                                                        float* __restrict__ out) {
    extern __shared__ __half smemh[];
    __half* As = smemh;             // [128][SST]
    __half* Bs = smemh + 128*SST;   // [128][SST]
    int tid = threadIdx.x;
    int bn = blockIdx.x, bm = blockIdx.y;

    for (int i = tid; i < 128*26; i += 256) {
        int r = i/26, c = i%26;
        uint4 v = *(const uint4*)(g_A16 + (size_t)(bm*128 + r)*KP + c*8);
        *(uint4*)(As + r*SST + c*8) = v;
    }
    for (int i = tid; i < 128*26; i += 256) {
        int r = i/26, c = i%26;
        int gn = bn*128 + r;
        uint4 v = make_uint4(0u,0u,0u,0u);
        if (gn < VOCAB) v = *(const uint4*)(g_B16 + (size_t)gn*KP + c*8);
        *(uint4*)(Bs + r*SST + c*8) = v;
    }
    __syncthreads();

    int warp = tid >> 5, lane = tid & 31;
    int wm = warp >> 2, wn = warp & 3;     // 2 x 4 warp grid, warp tile 64x32
    int lr = lane >> 2, lc = lane & 3;

    float acc[4][4][4];
    #pragma unroll
    for (int a=0;a<4;a++)
        #pragma unroll
        for (int b=0;b<4;b++)
            #pragma unroll
            for (int c=0;c<4;c++) acc[a][b][c]=0.f;

    const __half* Abase = As + (size_t)(wm*64 + lr)*SST + lc*2;
    const __half* Bbase = Bs + (size_t)(wn*32 + lr)*SST + lc*2;

    for (int ks = 0; ks < 13; ks++) {
        int k0 = ks*16;
        uint32_t a[4][4], bf[4][2];
        #pragma unroll
        for (int mf = 0; mf < 4; mf++) {
            const __half* p = Abase + (size_t)mf*16*SST + k0;
            a[mf][0] = *(const uint32_t*)(p);
            a[mf][1] = *(const uint32_t*)(p + 8*SST);
            a[mf][2] = *(const uint32_t*)(p + 8);
            a[mf][3] = *(const uint32_t*)(p + 8*SST + 8);
        }
        #pragma unroll
        for (int nf = 0; nf < 4; nf++) {
            const __half* p = Bbase + (size_t)nf*8*SST + k0;
            bf[nf][0] = *(const uint32_t*)(p);
            bf[nf][1] = *(const uint32_t*)(p + 8);
        }
        #pragma unroll
        for (int mf = 0; mf < 4; mf++)
            #pragma unroll
            for (int nf = 0; nf < 4; nf++)
                asm volatile(
                    "mma.sync.aligned.m16n8k16.row.col.f32.f16.f16.f32 "
                    "{%0,%1,%2,%3}, {%4,%5,%6,%7}, {%8,%9}, {%0,%1,%2,%3};"
                    : "+f"(acc[mf][nf][0]), "+f"(acc[mf][nf][1]),
                      "+f"(acc[mf][nf][2]), "+f"(acc[mf][nf][3])
                    : "r"(a[mf][0]), "r"(a[mf][1]), "r"(a[mf][2]), "r"(a[mf][3]),
                      "r"(bf[nf][0]), "r"(bf[nf][1]));
    }

    #pragma unroll
    for (int mf = 0; mf < 4; mf++) {
        int gm = bm*128 + wm*64 + mf*16 + lr;
        #pragma unroll
        for (int nf = 0; nf < 4; nf++) {
            int gn = bn*128 + wn*32 + nf*8 + lc*2;
            if (gn < VOCAB) {
                float b0 = bias[gn];
                out[(size_t)gm*VOCAB + gn]     = acc[mf][nf][0] + b0;
                out[(size_t)(gm+8)*VOCAB + gn] = acc[mf][nf][2] + b0;
            }
            if (gn+1 < VOCAB) {
                float b1 = bias[gn+1];
                out[(size_t)gm*VOCAB + gn+1]     = acc[mf][nf][1] + b1;
                out[(size_t)(gm+8)*VOCAB + gn+1] = acc[mf][nf][3] + b1;
            }
        }
    }
}

// ---------------- launch ----------------
extern "C" void kernel_launch(void* const* d_in, const int* in_sizes, int n_in,
                              void* d_out, int out_size) {
    (void)in_sizes; (void)n_in; (void)out_size;
    const int*   X      = (const int*)d_in[0];
    const float* hidden = (const float*)d_in[1];
    const float* embW   = (const float*)d_in[2];
    const float* Wih0   = (const float*)d_in[3];
    const float* Whh0   = (const float*)d_in[4];
    const float* Wih1   = (const float*)d_in[5];
    const float* Whh1   = (const float*)d_in[6];
    const float* decW   = (const float*)d_in[7];
    const float* decb   = (const float*)d_in[8];
    float* out = (float*)d_out;

    convB_kernel<<<(int)(((size_t)VOCAB*KP + 255)/256), 256>>>(decW);
    z0_kernel<<<S_LEN, 256>>>(X, embW, Wih0);

    rnn_fast_kernel<<<BATCH, RNN_THREADS>>>(Whh0, hidden, 0);
    z1_kernel<<<S_LEN, 256>>>(Wih1);
    rnn_fast_kernel<<<BATCH, RNN_THREADS>>>(Whh1, hidden + BATCH*HID, 1);

    hidden_kernel<<<(2*BATCH*HID + 255)/256, 256>>>(out);

    cudaFuncSetAttribute(decode_kernel, cudaFuncAttributeMaxDynamicSharedMemorySize,
                         2*128*SST*(int)sizeof(__half));
    dim3 grid((VOCAB + 127)/128, M_TOT/128);   // 393 x 32
    decode_kernel<<<grid, 256, 2*128*SST*(int)sizeof(__half)>>>(decb, out);
}

// round 17
// speedup vs baseline: 1.5982x; 1.1166x over previous
#include <cuda_runtime.h>
#include <cuda_fp16.h>
#include <cstdint>
#include <cstddef>

#define S_LEN 128
#define BATCH 32
#define HID   200
#define EMB   200
#define VOCAB 50257
#define KP    208              // K padded to multiple of 16 for mma
#define M_TOT (S_LEN*BATCH)    // 4096

// ---------------- scratch (device globals; no allocation) ----------------
__device__ float  g_Z0[M_TOT*HID];
__device__ float  g_Z1[M_TOT*HID];
__device__ float  g_Y0[M_TOT*HID];
__device__ float  g_Y1[M_TOT*HID];
__device__ __half g_A16[M_TOT*KP];          // pad cols [200,208) stay zero (static init, never written)
__device__ __half g_B16[(size_t)VOCAB*KP];

// ============== K1/K3 unified: Z = x @ W_ih^T with smem-staged W ==============
// The 106us z-kernel invariant across load-layouts was W-LDG latency (regs=32 ->
// MLP~2). Fix: stage W in 40-row chunks in smem, double-buffered, loaded
// cooperatively (256 threads x 8 LDG.128 -> high MLP, hidden under compute).
// Thread (b = tid&31, jsub = tid>>5); W read = warp-uniform broadcast LDS.128;
// x read = float4 from xs[b][k], row stride 212 floats (53 16B units, gcd(53,32)=1
// -> conflict-free). Summation grouping identical to R11 (bitwise-same results).
#define ZCH 40                  // j rows per W chunk; 5 chunks cover 200
#define XS_STRIDE 212
#define Z_SMEM ((BATCH*XS_STRIDE + 2*ZCH*HID) * (int)sizeof(float))   // 91136 B

__global__ __launch_bounds__(256) void z_proj_kernel(const float* __restrict__ Wih,
                                                     const int* __restrict__ X,
                                                     const float* __restrict__ embW,
                                                     int layer) {
    extern __shared__ __align__(16) float dsm[];
    float* xs = dsm;                       // [BATCH][XS_STRIDE]
    float* ws = dsm + BATCH*XS_STRIDE;     // [2][ZCH][HID]

    const int s = blockIdx.x, tid = threadIdx.x;

    // load x tile (layer 0: embedding gather; layer 1: y0)
    if (layer == 0) {
        for (int i = tid; i < BATCH*EMB; i += 256) {
            int b = i / EMB, d = i - b*EMB;
            xs[b*XS_STRIDE + d] = embW[(size_t)X[s*BATCH + b]*EMB + d];
        }
    } else {
        for (int i = tid; i < BATCH*HID; i += 256) {
            int b = i / HID, d = i - b*HID;
            xs[b*XS_STRIDE + d] = g_Y0[((size_t)s*BATCH + b)*HID + d];
        }
    }
    // load W chunk 0 cooperatively (2000 float4 over 256 threads)
    for (int i = tid; i < ZCH*50; i += 256) {
        int r = i / 50, c4 = i - r*50;
        ((float4*)(ws + r*HID))[c4] = ((const float4*)(Wih + (size_t)r*HID))[c4];
    }
    __syncthreads();

    const int b = tid & 31, jsub = tid >> 5;
    float* zrow = (layer ? g_Z1 : g_Z0) + (size_t)s*BATCH*HID;
    const float4* xr = (const float4*)(xs + b*XS_STRIDE);

    for (int c = 0; c < 5; c++) {
        const float* wbuf = ws + (c & 1)*ZCH*HID;
        if (c < 4) {   // prefetch next chunk into the other buffer
            float* wnext = ws + ((c + 1) & 1)*ZCH*HID;
            const float* wsrc = Wih + (size_t)(c + 1)*ZCH*HID;
            for (int i = tid; i < ZCH*50; i += 256) {
                int r = i / 50, c4 = i - r*50;
                ((float4*)(wnext + r*HID))[c4] = ((const float4*)(wsrc + (size_t)r*HID))[c4];
            }
        }
        #pragma unroll
        for (int jj = 0; jj < 5; jj++) {
            int jl = jsub*5 + jj;                       // 8 jsub x 5 = 40 rows
            const float4* wr = (const float4*)(wbuf + jl*HID);
            float a0 = 0.f, a1 = 0.f, a2 = 0.f, a3 = 0.f;
            #pragma unroll 10
            for (int k4 = 0; k4 < HID/4; k4++) {
                float4 w = wr[k4];
                float4 x = xr[k4];
                a0 += w.x*x.x;
                a1 += w.y*x.y;
                a2 += w.z*x.z;
                a3 += w.w*x.w;
            }
            zrow[b*HID + c*ZCH + jl] = (a0 + a1) + (a2 + a3);
        }
        __syncthreads();   // compute(c) done AND prefetch(c+1) done
    }
}

// ====== K2/K4: batch-parallel recurrence (R9/R11-proven, unchanged) ======
#define RNN_THREADS 416
__global__ __launch_bounds__(RNN_THREADS, 1)
void rnn_fast_kernel(const float* __restrict__ Whh, const float* __restrict__ h_init,
                     int layer) {
    __shared__ __align__(16) float hs[2][HID];
    const float* __restrict__ Z = layer ? g_Z1 : g_Z0;
    float* __restrict__ Y       = layer ? g_Y1 : g_Y0;

    const int b   = blockIdx.x;
    const int t0  = threadIdx.x;
    const int j   = t0 >> 1;
    const int kh  = t0 & 1;
    const bool valid = (j < HID);

    const float* wp = Whh + (size_t)(valid ? j : 0)*HID + kh*100;
    float w[100];
    #pragma unroll
    for (int i = 0; i < 100; i++) w[i] = wp[i];

    for (int i = t0; i < HID; i += RNN_THREADS) hs[0][i] = h_init[b*HID + i];
    __syncthreads();

    float zc = (valid && kh == 0) ? Z[(size_t)b*HID + j] : 0.f;

    for (int t = 0; t < S_LEN; t++) {
        const int cur = t & 1, nxt = cur ^ 1;
        float zn = 0.f;
        if (t + 1 < S_LEN && valid && kh == 0)
            zn = Z[((size_t)(t+1)*BATCH + b)*HID + j];

        float a0 = 0.f, a1 = 0.f, a2 = 0.f, a3 = 0.f;
        const float4* h4 = (const float4*)(hs[cur] + kh*100);
        #pragma unroll
        for (int i = 0; i < 25; i++) {
            float4 h = h4[i];
            a0 += w[4*i+0]*h.x;
            a1 += w[4*i+1]*h.y;
            a2 += w[4*i+2]*h.z;
            a3 += w[4*i+3]*h.w;
        }
        float acc = (a0 + a1) + (a2 + a3);
        float other = __shfl_down_sync(0xffffffffu, acc, 1);
        if (valid && kh == 0) {
            float v = tanhf(zc + acc + other);
            hs[nxt][j] = v;
            Y[((size_t)t*BATCH + b)*HID + j] = v;
            if (layer)
                g_A16[((size_t)t*BATCH + b)*KP + j] = __float2half_rn(v);
        }
        zc = zn;
        __syncthreads();
    }
}

// ---------------- convB: decoder weights -> fp16, K padded to 208 ----------------
__global__ void convB_kernel(const float* __restrict__ W) {
    size_t idx = (size_t)blockIdx.x*256 + threadIdx.x;
    if (idx >= (size_t)VOCAB*KP) return;
    size_t r = idx / KP; int c = (int)(idx % KP);
    g_B16[idx] = (c < HID) ? __float2half_rn(W[r*HID + c]) : __float2half_rn(0.f);
}

// ---------------- hidden_out = stack(y0[S-1], y1[S-1]) ----------------
__global__ void hidden_kernel(float* __restrict__ out) {
    int idx = blockIdx.x*256 + threadIdx.x;
    if (idx >= 2*BATCH*HID) return;
    int l = idx / (BATCH*HID), r = idx % (BATCH*HID);
    const float* Y = l ? g_Y1 : g_Y0;
    out[(size_t)M_TOT*VOCAB + idx] = Y[(S_LEN-1)*BATCH*HID + r];
}

// ====== K5: decode GEMM (R9/R11-proven scalar-LDS mma.sync version, unchanged) ======
// C[4096, 50257] = A16[4096, 208] * B16[50257, 208]^T + bias
#define SST 216   // smem row stride in halves (conflict-mitigating pad)
__global__ __launch_bounds__(256, 2) void decode_kernel(const float* __restrict__ bias,
                                                        float* __restrict__ out) {
    extern __shared__ __half smemh[];
    __half* As = smemh;             // [128][SST]
    __half* Bs = smemh + 128*SST;   // [128][SST]
    int tid = threadIdx.x;
    int bn = blockIdx.x, bm = blockIdx.y;

    for (int i = tid; i < 128*26; i += 256) {
        int r = i/26, c = i%26;
        uint4 v = *(const uint4*)(g_A16 + (size_t)(bm*128 + r)*KP + c*8);
        *(uint4*)(As + r*SST + c*8) = v;
    }
    for (int i = tid; i < 128*26; i += 256) {
        int r = i/26, c = i%26;
        int gn = bn*128 + r;
        uint4 v = make_uint4(0u,0u,0u,0u);
        if (gn < VOCAB) v = *(const uint4*)(g_B16 + (size_t)gn*KP + c*8);
        *(uint4*)(Bs + r*SST + c*8) = v;
    }
    __syncthreads();

    int warp = tid >> 5, lane = tid & 31;
    int wm = warp >> 2, wn = warp & 3;     // 2 x 4 warp grid, warp tile 64x32
    int lr = lane >> 2, lc = lane & 3;

    float acc[4][4][4];
    #pragma unroll
    for (int a=0;a<4;a++)
        #pragma unroll
        for (int b=0;b<4;b++)
            #pragma unroll
            for (int c=0;c<4;c++) acc[a][b][c]=0.f;

    const __half* Abase = As + (size_t)(wm*64 + lr)*SST + lc*2;
    const __half* Bbase = Bs + (size_t)(wn*32 + lr)*SST + lc*2;

    for (int ks = 0; ks < 13; ks++) {
        int k0 = ks*16;
        uint32_t a[4][4], bf[4][2];
        #pragma unroll
        for (int mf = 0; mf < 4; mf++) {
            const __half* p = Abase + (size_t)mf*16*SST + k0;
            a[mf][0] = *(const uint32_t*)(p);
            a[mf][1] = *(const uint32_t*)(p + 8*SST);
            a[mf][2] = *(const uint32_t*)(p + 8);
            a[mf][3] = *(const uint32_t*)(p + 8*SST + 8);
        }
        #pragma unroll
        for (int nf = 0; nf < 4; nf++) {
            const __half* p = Bbase + (size_t)nf*8*SST + k0;
            bf[nf][0] = *(const uint32_t*)(p);
            bf[nf][1] = *(const uint32_t*)(p + 8);
        }
        #pragma unroll
        for (int mf = 0; mf < 4; mf++)
            #pragma unroll
            for (int nf = 0; nf < 4; nf++)
                asm volatile(
                    "mma.sync.aligned.m16n8k16.row.col.f32.f16.f16.f32 "
                    "{%0,%1,%2,%3}, {%4,%5,%6,%7}, {%8,%9}, {%0,%1,%2,%3};"
                    : "+f"(acc[mf][nf][0]), "+f"(acc[mf][nf][1]),
                      "+f"(acc[mf][nf][2]), "+f"(acc[mf][nf][3])
                    : "r"(a[mf][0]), "r"(a[mf][1]), "r"(a[mf][2]), "r"(a[mf][3]),
                      "r"(bf[nf][0]), "r"(bf[nf][1]));
    }

    #pragma unroll
    for (int mf = 0; mf < 4; mf++) {
        int gm = bm*128 + wm*64 + mf*16 + lr;
        #pragma unroll
        for (int nf = 0; nf < 4; nf++) {
            int gn = bn*128 + wn*32 + nf*8 + lc*2;
            if (gn < VOCAB) {
                float b0 = bias[gn];
                out[(size_t)gm*VOCAB + gn]     = acc[mf][nf][0] + b0;
                out[(size_t)(gm+8)*VOCAB + gn] = acc[mf][nf][2] + b0;
            }
            if (gn+1 < VOCAB) {
                float b1 = bias[gn+1];
                out[(size_t)gm*VOCAB + gn+1]     = acc[mf][nf][1] + b1;
                out[(size_t)(gm+8)*VOCAB + gn+1] = acc[mf][nf][3] + b1;
            }
        }
    }
}

// ---------------- launch ----------------
extern "C" void kernel_launch(void* const* d_in, const int* in_sizes, int n_in,
                              void* d_out, int out_size) {
    (void)in_sizes; (void)n_in; (void)out_size;
    const int*   X      = (const int*)d_in[0];
    const float* hidden = (const float*)d_in[1];
    const float* embW   = (const float*)d_in[2];
    const float* Wih0   = (const float*)d_in[3];
    const float* Whh0   = (const float*)d_in[4];
    const float* Wih1   = (const float*)d_in[5];
    const float* Whh1   = (const float*)d_in[6];
    const float* decW   = (const float*)d_in[7];
    const float* decb   = (const float*)d_in[8];
    float* out = (float*)d_out;

    cudaFuncSetAttribute(z_proj_kernel, cudaFuncAttributeMaxDynamicSharedMemorySize,
                         Z_SMEM);

    convB_kernel<<<(int)(((size_t)VOCAB*KP + 255)/256), 256>>>(decW);
    z_proj_kernel<<<S_LEN, 256, Z_SMEM>>>(Wih0, X, embW, 0);

    rnn_fast_kernel<<<BATCH, RNN_THREADS>>>(Whh0, hidden, 0);
    z_proj_kernel<<<S_LEN, 256, Z_SMEM>>>(Wih1, X, embW, 1);
    rnn_fast_kernel<<<BATCH, RNN_THREADS>>>(Whh1, hidden + BATCH*HID, 1);

    hidden_kernel<<<(2*BATCH*HID + 255)/256, 256>>>(out);

    cudaFuncSetAttribute(decode_kernel, cudaFuncAttributeMaxDynamicSharedMemorySize,
                         2*128*SST*(int)sizeof(__half));
    dim3 grid((VOCAB + 127)/128, M_TOT/128);   // 393 x 32
    decode_kernel<<<grid, 256, 2*128*SST*(int)sizeof(__half)>>>(decb, out);
}